// round 1
// baseline (speedup 1.0000x reference)
#include <cuda_runtime.h>
#include <math.h>

// ============================================================================
// Scratch (static device memory — no allocations allowed)
// ============================================================================
// layout [b, N, C] pixel-major everywhere.
static constexpr size_t SZ_X1A = (size_t)2*784*64;
static constexpr size_t SZ_X2A = (size_t)2*196*64;
static constexpr size_t SZ_OA  = (size_t)2*784*64;
static constexpr size_t SZ_RMA = (size_t)2*784;
static constexpr size_t SZ_RSA = (size_t)2*784;
static constexpr size_t SZ_X1B = (size_t)2*3136*64;
static constexpr size_t SZ_X2B = (size_t)2*784*64;
static constexpr size_t SZ_OB  = (size_t)2*3136*64;
static constexpr size_t SZ_RMB = (size_t)2*3136;
static constexpr size_t SZ_RSB = (size_t)2*3136;
static constexpr size_t SZ_X1C = (size_t)2*12544*32;
static constexpr size_t SZ_X2C = (size_t)2*3136*32;
static constexpr size_t SZ_OC  = (size_t)2*12544*32;
static constexpr size_t SZ_RMC = (size_t)2*12544;
static constexpr size_t SZ_RSC = (size_t)2*12544;
static constexpr size_t SZ_Y1  = (size_t)2*3136*32;
static constexpr size_t SZ_Y2  = (size_t)2*12544*16;
static constexpr size_t SZ_Y3  = (size_t)2*50176*8;
static constexpr size_t SZ_MZ  = 4;

static constexpr size_t OFF_X1A = 0;
static constexpr size_t OFF_X2A = OFF_X1A + SZ_X1A;
static constexpr size_t OFF_OA  = OFF_X2A + SZ_X2A;
static constexpr size_t OFF_RMA = OFF_OA  + SZ_OA;
static constexpr size_t OFF_RSA = OFF_RMA + SZ_RMA;
static constexpr size_t OFF_X1B = OFF_RSA + SZ_RSA;
static constexpr size_t OFF_X2B = OFF_X1B + SZ_X1B;
static constexpr size_t OFF_OB  = OFF_X2B + SZ_X2B;
static constexpr size_t OFF_RMB = OFF_OB  + SZ_OB;
static constexpr size_t OFF_RSB = OFF_RMB + SZ_RMB;
static constexpr size_t OFF_X1C = OFF_RSB + SZ_RSB;
static constexpr size_t OFF_X2C = OFF_X1C + SZ_X1C;
static constexpr size_t OFF_OC  = OFF_X2C + SZ_X2C;
static constexpr size_t OFF_RMC = OFF_OC  + SZ_OC;
static constexpr size_t OFF_RSC = OFF_RMC + SZ_RMC;
static constexpr size_t OFF_Y1  = OFF_RSC + SZ_RSC;
static constexpr size_t OFF_Y2  = OFF_Y1  + SZ_Y1;
static constexpr size_t OFF_Y3  = OFF_Y2  + SZ_Y2;
static constexpr size_t OFF_MZ  = OFF_Y3  + SZ_Y3;
static constexpr size_t SCRATCH_TOTAL = OFF_MZ + SZ_MZ;

__device__ float g_scratch[SCRATCH_TOTAL];

// ============================================================================
// Projection: out[b,n,h] = sum_c X(b,n,c) * W[c,h]
// Handles both NCHW sources (sn=1, sc=N) and pixel-major (sn=C, sc=1).
// ============================================================================
template<int C, int H>
__global__ void __launch_bounds__(256) proj_kernel(
    const float* __restrict__ X, const float* __restrict__ W,
    float* __restrict__ out, int N, int sn, int sc, size_t bstride)
{
    __shared__ float sw[C*H];
    const int tid = threadIdx.x;
    for (int i = tid; i < C*H; i += 256) sw[i] = W[i];
    __syncthreads();
    const int b = blockIdx.y;
    const int n = blockIdx.x * 32 + (tid & 31);
    const int ty = tid >> 5;            // 0..7
    constexpr int HP = H / 8;
    if (n >= N) return;
    const float* xb = X + (size_t)b * bstride;
    float acc[HP];
#pragma unroll
    for (int k = 0; k < HP; k++) acc[k] = 0.f;
    for (int c = 0; c < C; c++) {
        float v = xb[(size_t)n * sn + (size_t)c * sc];
        const float* wr = &sw[c*H + ty*HP];
#pragma unroll
        for (int k = 0; k < HP; k++) acc[k] += v * wr[k];
    }
    float* ob = out + ((size_t)b * N + n) * H + ty * HP;
#pragma unroll
    for (int k = 0; k < HP; k++) ob[k] = acc[k];
}

// ============================================================================
// Flash-style CSA core: per-row online softmax over a[n,m] = <x1[n], x2[m]>.
// Emits unnormalized O[n,h] = sum_m exp(a[n,m]-rowmax[n]) x2[m,h], plus
// rowmax/rowsum for the later global renormalization.
// ============================================================================
template<int H>
__global__ void __launch_bounds__(256) flash_kernel(
    const float* __restrict__ X1, const float* __restrict__ X2,
    float* __restrict__ Oout, float* __restrict__ rowmax, float* __restrict__ rowsum,
    int N1, int N2)
{
    constexpr int RB = 64, MB = 64;
    constexpr int PX = H + 4;            // padded pitch (floats), keeps 16B align
    constexpr int PS = MB + 4;
    constexpr int CPT = H / 16;          // O-columns per thread (4 or 2)
    constexpr int H4 = H / 4;
    extern __shared__ float sm[];
    float* sX1 = sm;                     // RB*PX
    float* sX2 = sX1 + RB*PX;            // MB*PX
    float* sS  = sX2 + MB*PX;            // RB*PS
    float* srm = sS  + RB*PS;            // RB
    float* srs = srm + RB;               // RB
    float* ssc = srs + RB;               // RB

    const int b = blockIdx.y;
    const int row0 = blockIdx.x * RB;
    const float* x1 = X1 + (size_t)b * N1 * H;
    const float* x2 = X2 + (size_t)b * N2 * H;
    const int tid = threadIdx.x;

    // Load X1 row tile (zero-fill OOB rows)
    for (int i = tid; i < RB * H4; i += 256) {
        int r = i / H4, c = i % H4;
        float4 v = make_float4(0.f, 0.f, 0.f, 0.f);
        int gr = row0 + r;
        if (gr < N1) v = *reinterpret_cast<const float4*>(&x1[(size_t)gr * H + c * 4]);
        *reinterpret_cast<float4*>(&sX1[r * PX + c * 4]) = v;
    }
    if (tid < RB) { srm[tid] = -INFINITY; srs[tid] = 0.f; }

    float o[4][CPT];
#pragma unroll
    for (int r = 0; r < 4; r++)
#pragma unroll
        for (int c = 0; c < CPT; c++) o[r][c] = 0.f;

    const int ti = tid >> 4, tj = tid & 15;
    const int i0 = ti * 4;
    const int h0 = tj * CPT;

    for (int mb = 0; mb < N2; mb += MB) {
        __syncthreads();
        // Load X2 tile
        for (int i = tid; i < MB * H4; i += 256) {
            int r = i / H4, c = i % H4;
            float4 v = make_float4(0.f, 0.f, 0.f, 0.f);
            int gm = mb + r;
            if (gm < N2) v = *reinterpret_cast<const float4*>(&x2[(size_t)gm * H + c * 4]);
            *reinterpret_cast<float4*>(&sX2[r * PX + c * 4]) = v;
        }
        __syncthreads();

        // ---- S = X1tile . X2tile^T  (4x4 micro-tiles, cols interleaved by 16)
        float acc[4][4];
#pragma unroll
        for (int r = 0; r < 4; r++)
#pragma unroll
            for (int c = 0; c < 4; c++) acc[r][c] = 0.f;
#pragma unroll
        for (int h = 0; h < H; h += 4) {
            float4 a[4], bb[4];
#pragma unroll
            for (int r = 0; r < 4; r++)
                a[r] = *reinterpret_cast<const float4*>(&sX1[(i0 + r) * PX + h]);
#pragma unroll
            for (int c = 0; c < 4; c++)
                bb[c] = *reinterpret_cast<const float4*>(&sX2[(tj + 16 * c) * PX + h]);
#pragma unroll
            for (int r = 0; r < 4; r++)
#pragma unroll
                for (int c = 0; c < 4; c++)
                    acc[r][c] += a[r].x*bb[c].x + a[r].y*bb[c].y + a[r].z*bb[c].z + a[r].w*bb[c].w;
        }
#pragma unroll
        for (int r = 0; r < 4; r++)
#pragma unroll
            for (int c = 0; c < 4; c++)
                sS[(i0 + r) * PS + tj + 16 * c] = acc[r][c];
        __syncthreads();

        // ---- online softmax update (4 lanes per row, shfl combine)
        {
            const int r = tid >> 2;
            const int part = tid & 3;
            const int limit = N2 - mb;
            float vals[16];
            float mx = -INFINITY;
#pragma unroll
            for (int k = 0; k < 16; k++) {
                int j = part * 16 + k;
                float v = (j < limit) ? sS[r * PS + j] : -INFINITY;
                vals[k] = v;
                mx = fmaxf(mx, v);
            }
            mx = fmaxf(mx, __shfl_xor_sync(0xffffffffu, mx, 1));
            mx = fmaxf(mx, __shfl_xor_sync(0xffffffffu, mx, 2));
            float mold = srm[r];
            float mnew = fmaxf(mold, mx);
            float sum = 0.f;
#pragma unroll
            for (int k = 0; k < 16; k++) {
                float p = __expf(vals[k] - mnew);
                sum += p;
                sS[r * PS + part * 16 + k] = p;
            }
            sum += __shfl_xor_sync(0xffffffffu, sum, 1);
            sum += __shfl_xor_sync(0xffffffffu, sum, 2);
            if (part == 0) {
                float scale = __expf(mold - mnew);
                srs[r] = srs[r] * scale + sum;
                srm[r] = mnew;
                ssc[r] = scale;
            }
        }
        __syncthreads();

        // ---- O rescale + accumulate: O += P . X2tile
#pragma unroll
        for (int r = 0; r < 4; r++) {
            float s = ssc[i0 + r];
#pragma unroll
            for (int c = 0; c < CPT; c++) o[r][c] *= s;
        }
#pragma unroll
        for (int j = 0; j < MB; j += 4) {
            float4 p[4];
#pragma unroll
            for (int r = 0; r < 4; r++)
                p[r] = *reinterpret_cast<const float4*>(&sS[(i0 + r) * PS + j]);
            float bb[4][CPT];
#pragma unroll
            for (int jj = 0; jj < 4; jj++) {
                if constexpr (CPT == 4) {
                    float4 t = *reinterpret_cast<const float4*>(&sX2[(j + jj) * PX + h0]);
                    bb[jj][0] = t.x; bb[jj][1] = t.y; bb[jj][2] = t.z; bb[jj][3] = t.w;
                } else {
                    float2 t = *reinterpret_cast<const float2*>(&sX2[(j + jj) * PX + h0]);
                    bb[jj][0] = t.x; bb[jj][1] = t.y;
                }
            }
#pragma unroll
            for (int r = 0; r < 4; r++)
#pragma unroll
                for (int c = 0; c < CPT; c++)
                    o[r][c] += p[r].x*bb[0][c] + p[r].y*bb[1][c] + p[r].z*bb[2][c] + p[r].w*bb[3][c];
        }
    }

    // store O (unnormalized), rowmax, rowsum
#pragma unroll
    for (int r = 0; r < 4; r++) {
        int gr = row0 + i0 + r;
        if (gr < N1) {
            float* dst = Oout + ((size_t)b * N1 + gr) * H + h0;
#pragma unroll
            for (int c = 0; c < CPT; c++) dst[c] = o[r][c];
        }
    }
    if (tid < RB) {
        int gr = row0 + tid;
        if (gr < N1) {
            rowmax[(size_t)b * N1 + gr] = srm[tid];
            rowsum[(size_t)b * N1 + gr] = srs[tid];
        }
    }
}

// ============================================================================
// Global softmax stats: M = max_n rowmax, Z = sum_n rowsum*exp(rowmax-M)
// ============================================================================
__global__ void __launch_bounds__(256) reduce_mz_kernel(
    const float* __restrict__ rm, const float* __restrict__ rs,
    float* __restrict__ MZ, int N1)
{
    __shared__ float red[256];
    const int b = blockIdx.x, tid = threadIdx.x;
    const float* rmb = rm + (size_t)b * N1;
    const float* rsb = rs + (size_t)b * N1;
    float mx = -INFINITY;
    for (int i = tid; i < N1; i += 256) mx = fmaxf(mx, rmb[i]);
    red[tid] = mx; __syncthreads();
    for (int s = 128; s > 0; s >>= 1) {
        if (tid < s) red[tid] = fmaxf(red[tid], red[tid + s]);
        __syncthreads();
    }
    const float M = red[0];
    __syncthreads();
    float z = 0.f;
    for (int i = tid; i < N1; i += 256) z += rsb[i] * __expf(rmb[i] - M);
    red[tid] = z; __syncthreads();
    for (int s = 128; s > 0; s >>= 1) {
        if (tid < s) red[tid] += red[tid + s];
        __syncthreads();
    }
    if (tid == 0) { MZ[b * 2] = M; MZ[b * 2 + 1] = red[0]; }
}

// In-place: O[n,h] = O[n,h]*exp(rowmax[n]-M)/Z + x1[n,h]
__global__ void __launch_bounds__(256) combine_kernel(
    float* __restrict__ O, const float* __restrict__ x1,
    const float* __restrict__ rm, const float* __restrict__ MZ,
    int N1, int H)
{
    const int b = blockIdx.y;
    const float M = MZ[b * 2];
    const float invZ = 1.f / MZ[b * 2 + 1];
    const size_t total = (size_t)N1 * H;
    const size_t idx = (size_t)blockIdx.x * 256 + threadIdx.x;
    if (idx >= total) return;
    const int n = (int)(idx / H);
    const float f = __expf(rm[(size_t)b * N1 + n] - M) * invZ;
    const size_t g = (size_t)b * total + idx;
    O[g] = O[g] * f + x1[g];
}

// ============================================================================
// MSR: out = (base + up2(prev)) -> fc1 -> relu6 -> fc2, per pixel.
// base may be absent (template flag). prev is [b, Hin*Hin, CIN] pixel-major.
// ============================================================================
template<int CIN, int CHID, int COUT, bool HASBASE>
__global__ void msr_kernel(
    const float* __restrict__ base, const float* __restrict__ prev,
    const float* __restrict__ w1, const float* __restrict__ b1,
    const float* __restrict__ w2, const float* __restrict__ b2,
    float* __restrict__ out, int Hout, int Hin)
{
    __shared__ float sw1[CIN * CHID];
    __shared__ float sw2[CHID * COUT];
    __shared__ float sb1[CHID];
    __shared__ float sb2[COUT];
    const int tid = threadIdx.x;
    for (int i = tid; i < CIN * CHID; i += 128) sw1[i] = w1[i];
    for (int i = tid; i < CHID * COUT; i += 128) sw2[i] = w2[i];
    if (tid < CHID) sb1[tid] = b1[tid];
    if (tid < COUT) sb2[tid] = b2[tid];
    __syncthreads();

    const int b = blockIdx.y;
    const int N = Hout * Hout;
    const int n = blockIdx.x * 128 + tid;
    if (n >= N) return;
    const int oy = n / Hout, ox = n % Hout;

    // bilinear x2, half-pixel centers, edge-clamped (== jax/torch for 2-tap)
    int y0 = (oy - 1) >> 1; int y1v = y0 + 1;
    const float wy1 = (oy & 1) ? 0.25f : 0.75f; const float wy0 = 1.f - wy1;
    y0 = max(y0, 0); y1v = min(y1v, Hin - 1);
    int x0 = (ox - 1) >> 1; int x1v = x0 + 1;
    const float wx1 = (ox & 1) ? 0.25f : 0.75f; const float wx0 = 1.f - wx1;
    x0 = max(x0, 0); x1v = min(x1v, Hin - 1);

    const size_t pb = (size_t)b * Hin * Hin;
    const float* p00 = prev + (pb + (size_t)y0  * Hin + x0 ) * CIN;
    const float* p01 = prev + (pb + (size_t)y0  * Hin + x1v) * CIN;
    const float* p10 = prev + (pb + (size_t)y1v * Hin + x0 ) * CIN;
    const float* p11 = prev + (pb + (size_t)y1v * Hin + x1v) * CIN;
    const float w00 = wy0 * wx0, w01 = wy0 * wx1, w10 = wy1 * wx0, w11 = wy1 * wx1;
    const float* bp = HASBASE ? (base + ((size_t)b * N + n) * CIN) : nullptr;

    float hid[CHID];
#pragma unroll
    for (int j = 0; j < CHID; j++) hid[j] = sb1[j];
    for (int c = 0; c < CIN; c++) {
        float v = w00 * p00[c] + w01 * p01[c] + w10 * p10[c] + w11 * p11[c];
        if (HASBASE) v += bp[c];
        const float* wr = &sw1[c * CHID];
#pragma unroll
        for (int j = 0; j < CHID; j++) hid[j] += v * wr[j];
    }
#pragma unroll
    for (int j = 0; j < CHID; j++) hid[j] = fminf(fmaxf(hid[j], 0.f), 6.f);

    float accv[COUT];
#pragma unroll
    for (int k = 0; k < COUT; k++) accv[k] = sb2[k];
#pragma unroll
    for (int j = 0; j < CHID; j++) {
        const float hv = hid[j];
        const float* wr = &sw2[j * COUT];
#pragma unroll
        for (int k = 0; k < COUT; k++) accv[k] += hv * wr[k];
    }
    float* ob = out + ((size_t)b * N + n) * COUT;
#pragma unroll
    for (int k = 0; k < COUT; k++) ob[k] = accv[k];
}

// ============================================================================
// Launch
// ============================================================================
static inline int ceil_div(int a, int b) { return (a + b - 1) / b; }

extern "C" void kernel_launch(void* const* d_in, const int* in_sizes, int n_in,
                              void* d_out, int out_size)
{
    const float* f0 = (const float*)d_in[0];   // [2,160,14,14]
    const float* f1 = (const float*)d_in[1];   // [2,128,28,28]
    const float* f2 = (const float*)d_in[2];   // [2,64,56,56]
    const float* f3 = (const float*)d_in[3];   // [2,32,112,112]
    const float* cas1_w1 = (const float*)d_in[4];
    const float* cas1_w2 = (const float*)d_in[5];
    const float* cas2_w1 = (const float*)d_in[6];
    const float* cas2_w2 = (const float*)d_in[7];
    const float* cas3_w1 = (const float*)d_in[8];
    const float* cas3_w2 = (const float*)d_in[9];
    const float* m1w1 = (const float*)d_in[10]; const float* m1b1 = (const float*)d_in[11];
    const float* m1w2 = (const float*)d_in[12]; const float* m1b2 = (const float*)d_in[13];
    const float* m2w1 = (const float*)d_in[14]; const float* m2b1 = (const float*)d_in[15];
    const float* m2w2 = (const float*)d_in[16]; const float* m2b2 = (const float*)d_in[17];
    const float* m3w1 = (const float*)d_in[18]; const float* m3b1 = (const float*)d_in[19];
    const float* m3w2 = (const float*)d_in[20]; const float* m3b2 = (const float*)d_in[21];
    const float* m4w1 = (const float*)d_in[22]; const float* m4b1 = (const float*)d_in[23];
    const float* m4w2 = (const float*)d_in[24]; const float* m4b2 = (const float*)d_in[25];
    float* outp = (float*)d_out;

    float* S = nullptr;
    cudaGetSymbolAddress((void**)&S, g_scratch);
    float* x1a = S + OFF_X1A; float* x2a = S + OFF_X2A; float* Oa = S + OFF_OA;
    float* rma = S + OFF_RMA; float* rsa = S + OFF_RSA;
    float* x1b = S + OFF_X1B; float* x2b = S + OFF_X2B; float* Ob = S + OFF_OB;
    float* rmb = S + OFF_RMB; float* rsb = S + OFF_RSB;
    float* x1c = S + OFF_X1C; float* x2c = S + OFF_X2C; float* Oc = S + OFF_OC;
    float* rmc = S + OFF_RMC; float* rsc = S + OFF_RSC;
    float* y1 = S + OFF_Y1; float* y2 = S + OFF_Y2; float* y3 = S + OFF_Y3;
    float* MZ = S + OFF_MZ;

    // dynamic smem sizes for flash kernels
    const int smem64 = (64*68*3 + 3*64) * (int)sizeof(float);   // 52992
    const int smem32 = (64*36*2 + 64*68 + 3*64) * (int)sizeof(float); // 36608
    cudaFuncSetAttribute((const void*)flash_kernel<64>,
                         cudaFuncAttributeMaxDynamicSharedMemorySize, smem64);
    cudaFuncSetAttribute((const void*)flash_kernel<32>,
                         cudaFuncAttributeMaxDynamicSharedMemorySize, smem32);

    // ---------------- CSA1: hr=f1 (N1=784,C=128), lr=f0 (N2=196,C=160), H=64
    proj_kernel<160,64><<<dim3(ceil_div(196,32),2), 256>>>(f0, cas1_w2, x2a, 196, 1, 196, (size_t)160*196);
    proj_kernel<128,64><<<dim3(ceil_div(784,32),2), 256>>>(f1, cas1_w1, x1a, 784, 1, 784, (size_t)128*784);
    flash_kernel<64><<<dim3(ceil_div(784,64),2), 256, smem64>>>(x1a, x2a, Oa, rma, rsa, 784, 196);
    reduce_mz_kernel<<<2, 256>>>(rma, rsa, MZ, 784);
    combine_kernel<<<dim3(ceil_div(784*64,256),2), 256>>>(Oa, x1a, rma, MZ, 784, 64);
    // Oa is now X1out: [2,784,64] (28x28, 64ch)

    // ---------------- CSA2: hr=f2 (N1=3136,C=64), lr=X1out (N2=784,C=64), H=64
    proj_kernel<64,64><<<dim3(ceil_div(3136,32),2), 256>>>(f2, cas2_w1, x1b, 3136, 1, 3136, (size_t)64*3136);
    proj_kernel<64,64><<<dim3(ceil_div(784,32),2), 256>>>(Oa, cas2_w2, x2b, 784, 64, 1, (size_t)784*64);
    flash_kernel<64><<<dim3(ceil_div(3136,64),2), 256, smem64>>>(x1b, x2b, Ob, rmb, rsb, 3136, 784);
    reduce_mz_kernel<<<2, 256>>>(rmb, rsb, MZ, 3136);
    combine_kernel<<<dim3(ceil_div(3136*64,256),2), 256>>>(Ob, x1b, rmb, MZ, 3136, 64);
    // Ob is now X2out: [2,3136,64] (56x56, 64ch)

    // ---------------- CSA3: hr=f3 (N1=12544,C=32), lr=X2out (N2=3136,C=64), H=32
    proj_kernel<32,32><<<dim3(ceil_div(12544,32),2), 256>>>(f3, cas3_w1, x1c, 12544, 1, 12544, (size_t)32*12544);
    proj_kernel<64,32><<<dim3(ceil_div(3136,32),2), 256>>>(Ob, cas3_w2, x2c, 3136, 64, 1, (size_t)3136*64);
    flash_kernel<32><<<dim3(ceil_div(12544,64),2), 256, smem32>>>(x1c, x2c, Oc, rmc, rsc, 12544, 3136);
    reduce_mz_kernel<<<2, 256>>>(rmc, rsc, MZ, 12544);
    combine_kernel<<<dim3(ceil_div(12544*32,256),2), 256>>>(Oc, x1c, rmc, MZ, 12544, 32);
    // Oc is now X3out: [2,12544,32] (112x112, 32ch)

    // ---------------- decoder
    // y1 = msr1(X2out + up2(X1out))  56x56, 64->64(relu6)->32
    msr_kernel<64,64,32,true><<<dim3(ceil_div(3136,128),2), 128>>>(
        Ob, Oa, m1w1, m1b1, m1w2, m1b2, y1, 56, 28);
    // y2 = msr2(X3out + up2(y1))     112x112, 32->32->16
    msr_kernel<32,32,16,true><<<dim3(ceil_div(12544,128),2), 128>>>(
        Oc, y1, m2w1, m2b1, m2w2, m2b2, y2, 112, 56);
    // y3 = msr3(up2(y2))             224x224, 16->16->8
    msr_kernel<16,16,8,false><<<dim3(ceil_div(50176,128),2), 128>>>(
        nullptr, y2, m3w1, m3b1, m3w2, m3b2, y3, 224, 112);
    // y4 = msr4(up2(y3))             448x448, 8->2->1  -> d_out
    msr_kernel<8,2,1,false><<<dim3(ceil_div(200704,128),2), 128>>>(
        nullptr, y3, m4w1, m4b1, m4w2, m4b2, outp, 448, 224);

    (void)in_sizes; (void)n_in; (void)out_size;
}

// round 2
// speedup vs baseline: 1.5434x; 1.5434x over previous
#include <cuda_runtime.h>
#include <math.h>
#include <stdint.h>

// ============================================================================
// Scratch (static device memory — no allocations allowed)
// ============================================================================
static constexpr size_t SZ_X1A = (size_t)2*784*64;
static constexpr size_t SZ_X2A = (size_t)2*196*64;
static constexpr size_t SZ_OA  = (size_t)2*784*64;
static constexpr size_t SZ_RMA = (size_t)2*784;
static constexpr size_t SZ_RSA = (size_t)2*784;
static constexpr size_t SZ_X1B = (size_t)2*3136*64;
static constexpr size_t SZ_X2B = (size_t)2*784*64;
static constexpr size_t SZ_OB  = (size_t)2*3136*64;
static constexpr size_t SZ_RMB = (size_t)2*3136;
static constexpr size_t SZ_RSB = (size_t)2*3136;
static constexpr size_t SZ_X1C = (size_t)2*12544*32;
static constexpr size_t SZ_X2C = (size_t)2*3136*32;
static constexpr size_t SZ_OC  = (size_t)2*12544*32;
static constexpr size_t SZ_RMC = (size_t)2*12544;
static constexpr size_t SZ_RSC = (size_t)2*12544;
static constexpr size_t SZ_Y1  = (size_t)2*3136*32;
static constexpr size_t SZ_Y2  = (size_t)2*12544*16;
static constexpr size_t SZ_Y3  = (size_t)2*50176*8;
static constexpr size_t SZ_MZ  = 4;

static constexpr size_t OFF_X1A = 0;
static constexpr size_t OFF_X2A = OFF_X1A + SZ_X1A;
static constexpr size_t OFF_OA  = OFF_X2A + SZ_X2A;
static constexpr size_t OFF_RMA = OFF_OA  + SZ_OA;
static constexpr size_t OFF_RSA = OFF_RMA + SZ_RMA;
static constexpr size_t OFF_X1B = OFF_RSA + SZ_RSA;
static constexpr size_t OFF_X2B = OFF_X1B + SZ_X1B;
static constexpr size_t OFF_OB  = OFF_X2B + SZ_X2B;
static constexpr size_t OFF_RMB = OFF_OB  + SZ_OB;
static constexpr size_t OFF_RSB = OFF_RMB + SZ_RMB;
static constexpr size_t OFF_X1C = OFF_RSB + SZ_RSB;
static constexpr size_t OFF_X2C = OFF_X1C + SZ_X1C;
static constexpr size_t OFF_OC  = OFF_X2C + SZ_X2C;
static constexpr size_t OFF_RMC = OFF_OC  + SZ_OC;
static constexpr size_t OFF_RSC = OFF_RMC + SZ_RMC;
static constexpr size_t OFF_Y1  = OFF_RSC + SZ_RSC;
static constexpr size_t OFF_Y2  = OFF_Y1  + SZ_Y1;
static constexpr size_t OFF_Y3  = OFF_Y2  + SZ_Y2;
static constexpr size_t OFF_MZ  = OFF_Y3  + SZ_Y3;
static constexpr size_t SCRATCH_TOTAL = OFF_MZ + SZ_MZ;

__device__ float g_scratch[SCRATCH_TOTAL];

__device__ __forceinline__ float to_tf32(float x) {
    uint32_t u;
    asm("cvt.rna.tf32.f32 %0, %1;" : "=r"(u) : "f"(x));
    return __uint_as_float(u);
}

#define MMA_TF32(d, a, b)                                                      \
    asm volatile(                                                              \
        "mma.sync.aligned.m16n8k8.row.col.f32.tf32.tf32.f32 "                  \
        "{%0,%1,%2,%3},{%4,%5,%6,%7},{%8,%9},{%0,%1,%2,%3};"                   \
        : "+f"((d)[0]), "+f"((d)[1]), "+f"((d)[2]), "+f"((d)[3])               \
        : "r"((a)[0]), "r"((a)[1]), "r"((a)[2]), "r"((a)[3]),                  \
          "r"((b)[0]), "r"((b)[1]))

// ============================================================================
// Projection: out[b,n,h] = sum_c X(b,n,c) * W[c,h]
// ============================================================================
template<int C, int H>
__global__ void __launch_bounds__(256) proj_kernel(
    const float* __restrict__ X, const float* __restrict__ W,
    float* __restrict__ out, int N, int sn, int sc, size_t bstride)
{
    __shared__ float sw[C*H];
    const int tid = threadIdx.x;
    for (int i = tid; i < C*H; i += 256) sw[i] = W[i];
    __syncthreads();
    const int b = blockIdx.y;
    const int n = blockIdx.x * 32 + (tid & 31);
    const int ty = tid >> 5;
    constexpr int HP = H / 8;
    if (n >= N) return;
    const float* xb = X + (size_t)b * bstride;
    float acc[HP];
#pragma unroll
    for (int k = 0; k < HP; k++) acc[k] = 0.f;
    for (int c = 0; c < C; c++) {
        float v = xb[(size_t)n * sn + (size_t)c * sc];
        const float* wr = &sw[c*H + ty*HP];
#pragma unroll
        for (int k = 0; k < HP; k++) acc[k] += v * wr[k];
    }
    float* ob = out + ((size_t)b * N + n) * H + ty * HP;
#pragma unroll
    for (int k = 0; k < HP; k++) ob[k] = acc[k];
}

// ============================================================================
// Flash CSA core on tensor cores (mma.sync m16n8k8 tf32, fp32 accum).
// Per-row online softmax; emits unnormalized O + rowmax/rowsum for the
// global-softmax renormalization pass.
//
// Block: 256 threads = 8 warps. Tile: RB rows x MB(=64) cols per iteration.
// Warp grid: NRG = RB/32 row-groups x NCG = 8/NRG col-groups.
// Each warp: S chunk 32 x (MB/NCG); O chunk 32 x (H/NCG).
// ============================================================================
template<int H, int RB>
__global__ void __launch_bounds__(256) flash_mma_kernel(
    const float* __restrict__ X1, const float* __restrict__ X2,
    float* __restrict__ Oout, float* __restrict__ rowmax, float* __restrict__ rowsum,
    int N1, int N2)
{
    constexpr int MB  = 64;
    constexpr int PH  = H + 4;
    constexpr int PP  = MB + 4;            // 68
    constexpr int NRG = RB / 32;
    constexpr int NCG = 8 / NRG;
    constexpr int SCW = MB / NCG;          // S cols per warp
    constexpr int SNT = SCW / 8;           // S n-tiles
    constexpr int OCW = H / NCG;           // O cols per warp
    constexpr int ONT = OCW / 8;           // O n-tiles
    constexpr int H4  = H / 4;
    static_assert(ONT >= 1 && SNT >= 1, "tile config");

    extern __shared__ float sm[];
    float* sX1   = sm;                     // RB*PH
    float* sX2   = sX1 + RB*PH;            // MB*PH
    float* sP    = sX2 + MB*PH;            // RB*PP
    float* srm   = sP  + RB*PP;            // RB
    float* srs   = srm + RB;               // RB
    float* ssc   = srs + RB;               // RB
    float* sPmax = ssc + RB;               // RB*NCG
    float* sPsum = sPmax + RB*NCG;         // RB*NCG

    const int b    = blockIdx.y;
    const int row0 = blockIdx.x * RB;
    const float* x1 = X1 + (size_t)b * N1 * H;
    const float* x2 = X2 + (size_t)b * N2 * H;
    const int tid  = threadIdx.x;
    const int w    = tid >> 5, lane = tid & 31;
    const int g    = lane >> 2, t4 = lane & 3;
    const int mg   = (w % NRG) * 32;       // warp row base
    const int cgi  = w / NRG;              // warp col-group

    // ---- load X1 row tile (tf32-rounded, zero-fill OOB)
    for (int i = tid; i < RB * H4; i += 256) {
        int r = i / H4, c = i % H4;
        float4 v = make_float4(0.f, 0.f, 0.f, 0.f);
        int gr = row0 + r;
        if (gr < N1) v = *reinterpret_cast<const float4*>(&x1[(size_t)gr * H + c * 4]);
        v.x = to_tf32(v.x); v.y = to_tf32(v.y); v.z = to_tf32(v.z); v.w = to_tf32(v.w);
        *reinterpret_cast<float4*>(&sX1[r * PH + c * 4]) = v;
    }
    if (tid < RB) { srm[tid] = -INFINITY; srs[tid] = 0.f; }

    float o[2][ONT][4];
#pragma unroll
    for (int mt = 0; mt < 2; mt++)
#pragma unroll
        for (int nt = 0; nt < ONT; nt++)
#pragma unroll
            for (int k = 0; k < 4; k++) o[mt][nt][k] = 0.f;

    for (int mb = 0; mb < N2; mb += MB) {
        __syncthreads();
        // ---- load X2 tile (tf32-rounded, zero-fill OOB)
        for (int i = tid; i < MB * H4; i += 256) {
            int r = i / H4, c = i % H4;
            float4 v = make_float4(0.f, 0.f, 0.f, 0.f);
            int gm = mb + r;
            if (gm < N2) v = *reinterpret_cast<const float4*>(&x2[(size_t)gm * H + c * 4]);
            v.x = to_tf32(v.x); v.y = to_tf32(v.y); v.z = to_tf32(v.z); v.w = to_tf32(v.w);
            *reinterpret_cast<float4*>(&sX2[r * PH + c * 4]) = v;
        }
        __syncthreads();

        // ---- S = X1 . X2^T on tensor cores
        float sacc[2][SNT][4];
#pragma unroll
        for (int mt = 0; mt < 2; mt++)
#pragma unroll
            for (int nt = 0; nt < SNT; nt++)
#pragma unroll
                for (int k = 0; k < 4; k++) sacc[mt][nt][k] = 0.f;

#pragma unroll
        for (int ks = 0; ks < H / 8; ks++) {
            uint32_t afr[2][4], bfr[SNT][2];
#pragma unroll
            for (int mt = 0; mt < 2; mt++) {
                int r = mg + mt * 16 + g;
                int c = ks * 8 + t4;
                afr[mt][0] = __float_as_uint(sX1[r * PH + c]);
                afr[mt][1] = __float_as_uint(sX1[(r + 8) * PH + c]);
                afr[mt][2] = __float_as_uint(sX1[r * PH + c + 4]);
                afr[mt][3] = __float_as_uint(sX1[(r + 8) * PH + c + 4]);
            }
#pragma unroll
            for (int nt = 0; nt < SNT; nt++) {
                int r = cgi * SCW + nt * 8 + g;
                int c = ks * 8 + t4;
                bfr[nt][0] = __float_as_uint(sX2[r * PH + c]);
                bfr[nt][1] = __float_as_uint(sX2[r * PH + c + 4]);
            }
#pragma unroll
            for (int mt = 0; mt < 2; mt++)
#pragma unroll
                for (int nt = 0; nt < SNT; nt++)
                    MMA_TF32(sacc[mt][nt], afr[mt], bfr[nt]);
        }

        const int limit = N2 - mb;   // valid cols this tile

        // ---- per-(row,warp) max  (rows owned: mg+16mt+g+8d)
        float rmx[2][2];
#pragma unroll
        for (int mt = 0; mt < 2; mt++)
#pragma unroll
            for (int d = 0; d < 2; d++) {
                float m = -INFINITY;
#pragma unroll
                for (int nt = 0; nt < SNT; nt++) {
                    int col = cgi * SCW + nt * 8 + 2 * t4;
                    float v0 = (col     < limit) ? sacc[mt][nt][2*d]   : -INFINITY;
                    float v1 = (col + 1 < limit) ? sacc[mt][nt][2*d+1] : -INFINITY;
                    m = fmaxf(m, fmaxf(v0, v1));
                }
                m = fmaxf(m, __shfl_xor_sync(0xffffffffu, m, 1));
                m = fmaxf(m, __shfl_xor_sync(0xffffffffu, m, 2));
                rmx[mt][d] = m;
            }
        if (t4 == 0) {
#pragma unroll
            for (int mt = 0; mt < 2; mt++)
#pragma unroll
                for (int d = 0; d < 2; d++)
                    sPmax[(mg + 16*mt + g + 8*d) * NCG + cgi] = rmx[mt][d];
        }
        __syncthreads();

        // ---- P = exp(S - mnew), write to sP (tf32-rounded), warp row-sums
#pragma unroll
        for (int mt = 0; mt < 2; mt++)
#pragma unroll
            for (int d = 0; d < 2; d++) {
                int row = mg + 16*mt + g + 8*d;
                float wm = sPmax[row * NCG];
#pragma unroll
                for (int c2 = 1; c2 < NCG; c2++) wm = fmaxf(wm, sPmax[row * NCG + c2]);
                float mnew = fmaxf(srm[row], wm);
                float s = 0.f;
#pragma unroll
                for (int nt = 0; nt < SNT; nt++) {
                    int col = cgi * SCW + nt * 8 + 2 * t4;
                    float p0 = (col     < limit) ? __expf(sacc[mt][nt][2*d]   - mnew) : 0.f;
                    float p1 = (col + 1 < limit) ? __expf(sacc[mt][nt][2*d+1] - mnew) : 0.f;
                    s += p0 + p1;
                    float2 pv = make_float2(to_tf32(p0), to_tf32(p1));
                    *reinterpret_cast<float2*>(&sP[row * PP + col]) = pv;
                }
                s += __shfl_xor_sync(0xffffffffu, s, 1);
                s += __shfl_xor_sync(0xffffffffu, s, 2);
                if (t4 == 0) sPsum[row * NCG + cgi] = s;
            }
        __syncthreads();

        // ---- per-row state update
        if (tid < RB) {
            int row = tid;
            float wm = sPmax[row * NCG];
#pragma unroll
            for (int c2 = 1; c2 < NCG; c2++) wm = fmaxf(wm, sPmax[row * NCG + c2]);
            float mold = srm[row];
            float mnew = fmaxf(mold, wm);
            float sum = 0.f;
#pragma unroll
            for (int c2 = 0; c2 < NCG; c2++) sum += sPsum[row * NCG + c2];
            float sc = __expf(mold - mnew);
            srs[row] = srs[row] * sc + sum;
            srm[row] = mnew;
            ssc[row] = sc;
        }
        __syncthreads();

        // ---- O rescale + O += P . X2 on tensor cores
#pragma unroll
        for (int mt = 0; mt < 2; mt++)
#pragma unroll
            for (int d = 0; d < 2; d++) {
                float sc = ssc[mg + 16*mt + g + 8*d];
#pragma unroll
                for (int nt = 0; nt < ONT; nt++) {
                    o[mt][nt][2*d]   *= sc;
                    o[mt][nt][2*d+1] *= sc;
                }
            }
#pragma unroll
        for (int ks = 0; ks < MB / 8; ks++) {
            uint32_t afr[2][4], bfr[ONT][2];
#pragma unroll
            for (int mt = 0; mt < 2; mt++) {
                int r = mg + mt * 16 + g;
                int c = ks * 8 + t4;
                afr[mt][0] = __float_as_uint(sP[r * PP + c]);
                afr[mt][1] = __float_as_uint(sP[(r + 8) * PP + c]);
                afr[mt][2] = __float_as_uint(sP[r * PP + c + 4]);
                afr[mt][3] = __float_as_uint(sP[(r + 8) * PP + c + 4]);
            }
#pragma unroll
            for (int nt = 0; nt < ONT; nt++) {
                int hcol = cgi * OCW + nt * 8 + g;
                bfr[nt][0] = __float_as_uint(sX2[(ks * 8 + t4) * PH + hcol]);
                bfr[nt][1] = __float_as_uint(sX2[(ks * 8 + t4 + 4) * PH + hcol]);
            }
#pragma unroll
            for (int mt = 0; mt < 2; mt++)
#pragma unroll
                for (int nt = 0; nt < ONT; nt++)
                    MMA_TF32(o[mt][nt], afr[mt], bfr[nt]);
        }
    }

    // ---- store O (unnormalized) + stats
#pragma unroll
    for (int mt = 0; mt < 2; mt++)
#pragma unroll
        for (int d = 0; d < 2; d++) {
            int row = mg + 16*mt + g + 8*d;
            int gr = row0 + row;
            if (gr < N1) {
#pragma unroll
                for (int nt = 0; nt < ONT; nt++) {
                    int col = cgi * OCW + nt * 8 + 2 * t4;
                    float2 v = make_float2(o[mt][nt][2*d], o[mt][nt][2*d+1]);
                    *reinterpret_cast<float2*>(&Oout[((size_t)b * N1 + gr) * H + col]) = v;
                }
            }
        }
    if (tid < RB) {
        int gr = row0 + tid;
        if (gr < N1) {
            rowmax[(size_t)b * N1 + gr] = srm[tid];
            rowsum[(size_t)b * N1 + gr] = srs[tid];
        }
    }
}

// ============================================================================
// Global softmax stats: M = max_n rowmax, Z = sum_n rowsum*exp(rowmax-M)
// ============================================================================
__global__ void __launch_bounds__(256) reduce_mz_kernel(
    const float* __restrict__ rm, const float* __restrict__ rs,
    float* __restrict__ MZ, int N1)
{
    __shared__ float red[256];
    const int b = blockIdx.x, tid = threadIdx.x;
    const float* rmb = rm + (size_t)b * N1;
    const float* rsb = rs + (size_t)b * N1;
    float mx = -INFINITY;
    for (int i = tid; i < N1; i += 256) mx = fmaxf(mx, rmb[i]);
    red[tid] = mx; __syncthreads();
    for (int s = 128; s > 0; s >>= 1) {
        if (tid < s) red[tid] = fmaxf(red[tid], red[tid + s]);
        __syncthreads();
    }
    const float M = red[0];
    __syncthreads();
    float z = 0.f;
    for (int i = tid; i < N1; i += 256) z += rsb[i] * __expf(rmb[i] - M);
    red[tid] = z; __syncthreads();
    for (int s = 128; s > 0; s >>= 1) {
        if (tid < s) red[tid] += red[tid + s];
        __syncthreads();
    }
    if (tid == 0) { MZ[b * 2] = M; MZ[b * 2 + 1] = red[0]; }
}

// In-place: O[n,h] = O[n,h]*exp(rowmax[n]-M)/Z + x1[n,h]
__global__ void __launch_bounds__(256) combine_kernel(
    float* __restrict__ O, const float* __restrict__ x1,
    const float* __restrict__ rm, const float* __restrict__ MZ,
    int N1, int H)
{
    const int b = blockIdx.y;
    const float M = MZ[b * 2];
    const float invZ = 1.f / MZ[b * 2 + 1];
    const size_t total = (size_t)N1 * H;
    const size_t idx = (size_t)blockIdx.x * 256 + threadIdx.x;
    if (idx >= total) return;
    const int n = (int)(idx / H);
    const float f = __expf(rm[(size_t)b * N1 + n] - M) * invZ;
    const size_t g = (size_t)b * total + idx;
    O[g] = O[g] * f + x1[g];
}

// ============================================================================
// MSR: out = (base + up2(prev)) -> fc1 -> relu6 -> fc2, per pixel.
// ============================================================================
template<int CIN, int CHID, int COUT, bool HASBASE>
__global__ void msr_kernel(
    const float* __restrict__ base, const float* __restrict__ prev,
    const float* __restrict__ w1, const float* __restrict__ b1,
    const float* __restrict__ w2, const float* __restrict__ b2,
    float* __restrict__ out, int Hout, int Hin)
{
    __shared__ float sw1[CIN * CHID];
    __shared__ float sw2[CHID * COUT];
    __shared__ float sb1[CHID];
    __shared__ float sb2[COUT];
    const int tid = threadIdx.x;
    for (int i = tid; i < CIN * CHID; i += 128) sw1[i] = w1[i];
    for (int i = tid; i < CHID * COUT; i += 128) sw2[i] = w2[i];
    if (tid < CHID) sb1[tid] = b1[tid];
    if (tid < COUT) sb2[tid] = b2[tid];
    __syncthreads();

    const int b = blockIdx.y;
    const int N = Hout * Hout;
    const int n = blockIdx.x * 128 + tid;
    if (n >= N) return;
    const int oy = n / Hout, ox = n % Hout;

    int y0 = (oy - 1) >> 1; int y1v = y0 + 1;
    const float wy1 = (oy & 1) ? 0.25f : 0.75f; const float wy0 = 1.f - wy1;
    y0 = max(y0, 0); y1v = min(y1v, Hin - 1);
    int x0 = (ox - 1) >> 1; int x1v = x0 + 1;
    const float wx1 = (ox & 1) ? 0.25f : 0.75f; const float wx0 = 1.f - wx1;
    x0 = max(x0, 0); x1v = min(x1v, Hin - 1);

    const size_t pb = (size_t)b * Hin * Hin;
    const float* p00 = prev + (pb + (size_t)y0  * Hin + x0 ) * CIN;
    const float* p01 = prev + (pb + (size_t)y0  * Hin + x1v) * CIN;
    const float* p10 = prev + (pb + (size_t)y1v * Hin + x0 ) * CIN;
    const float* p11 = prev + (pb + (size_t)y1v * Hin + x1v) * CIN;
    const float w00 = wy0 * wx0, w01 = wy0 * wx1, w10 = wy1 * wx0, w11 = wy1 * wx1;
    const float* bp = HASBASE ? (base + ((size_t)b * N + n) * CIN) : nullptr;

    float hid[CHID];
#pragma unroll
    for (int j = 0; j < CHID; j++) hid[j] = sb1[j];
    for (int c = 0; c < CIN; c++) {
        float v = w00 * p00[c] + w01 * p01[c] + w10 * p10[c] + w11 * p11[c];
        if (HASBASE) v += bp[c];
        const float* wr = &sw1[c * CHID];
#pragma unroll
        for (int j = 0; j < CHID; j++) hid[j] += v * wr[j];
    }
#pragma unroll
    for (int j = 0; j < CHID; j++) hid[j] = fminf(fmaxf(hid[j], 0.f), 6.f);

    float accv[COUT];
#pragma unroll
    for (int k = 0; k < COUT; k++) accv[k] = sb2[k];
#pragma unroll
    for (int j = 0; j < CHID; j++) {
        const float hv = hid[j];
        const float* wr = &sw2[j * COUT];
#pragma unroll
        for (int k = 0; k < COUT; k++) accv[k] += hv * wr[k];
    }
    float* ob = out + ((size_t)b * N + n) * COUT;
#pragma unroll
    for (int k = 0; k < COUT; k++) ob[k] = accv[k];
}

// ============================================================================
// Launch
// ============================================================================
static inline int ceil_div(int a, int b) { return (a + b - 1) / b; }

template<int H, int RB>
static inline int flash_smem_bytes() {
    constexpr int MB = 64, PH = H + 4, PP = MB + 4;
    constexpr int NCG = 8 / (RB / 32);
    return (RB*PH + MB*PH + RB*PP + 3*RB + 2*RB*NCG) * (int)sizeof(float);
}

extern "C" void kernel_launch(void* const* d_in, const int* in_sizes, int n_in,
                              void* d_out, int out_size)
{
    const float* f0 = (const float*)d_in[0];   // [2,160,14,14]
    const float* f1 = (const float*)d_in[1];   // [2,128,28,28]
    const float* f2 = (const float*)d_in[2];   // [2,64,56,56]
    const float* f3 = (const float*)d_in[3];   // [2,32,112,112]
    const float* cas1_w1 = (const float*)d_in[4];
    const float* cas1_w2 = (const float*)d_in[5];
    const float* cas2_w1 = (const float*)d_in[6];
    const float* cas2_w2 = (const float*)d_in[7];
    const float* cas3_w1 = (const float*)d_in[8];
    const float* cas3_w2 = (const float*)d_in[9];
    const float* m1w1 = (const float*)d_in[10]; const float* m1b1 = (const float*)d_in[11];
    const float* m1w2 = (const float*)d_in[12]; const float* m1b2 = (const float*)d_in[13];
    const float* m2w1 = (const float*)d_in[14]; const float* m2b1 = (const float*)d_in[15];
    const float* m2w2 = (const float*)d_in[16]; const float* m2b2 = (const float*)d_in[17];
    const float* m3w1 = (const float*)d_in[18]; const float* m3b1 = (const float*)d_in[19];
    const float* m3w2 = (const float*)d_in[20]; const float* m3b2 = (const float*)d_in[21];
    const float* m4w1 = (const float*)d_in[22]; const float* m4b1 = (const float*)d_in[23];
    const float* m4w2 = (const float*)d_in[24]; const float* m4b2 = (const float*)d_in[25];
    float* outp = (float*)d_out;

    float* S = nullptr;
    cudaGetSymbolAddress((void**)&S, g_scratch);
    float* x1a = S + OFF_X1A; float* x2a = S + OFF_X2A; float* Oa = S + OFF_OA;
    float* rma = S + OFF_RMA; float* rsa = S + OFF_RSA;
    float* x1b = S + OFF_X1B; float* x2b = S + OFF_X2B; float* Ob = S + OFF_OB;
    float* rmb = S + OFF_RMB; float* rsb = S + OFF_RSB;
    float* x1c = S + OFF_X1C; float* x2c = S + OFF_X2C; float* Oc = S + OFF_OC;
    float* rmc = S + OFF_RMC; float* rsc = S + OFF_RSC;
    float* y1 = S + OFF_Y1; float* y2 = S + OFF_Y2; float* y3 = S + OFF_Y3;
    float* MZ = S + OFF_MZ;

    const int smem64 = flash_smem_bytes<64,64>();   // ~55KB
    const int smem32 = flash_smem_bytes<32,64>();   // ~39KB
    cudaFuncSetAttribute((const void*)flash_mma_kernel<64,64>,
                         cudaFuncAttributeMaxDynamicSharedMemorySize, smem64);
    cudaFuncSetAttribute((const void*)flash_mma_kernel<32,64>,
                         cudaFuncAttributeMaxDynamicSharedMemorySize, smem32);

    // ---------------- CSA1: hr=f1 (N1=784,C=128), lr=f0 (N2=196,C=160), H=64
    proj_kernel<160,64><<<dim3(ceil_div(196,32),2), 256>>>(f0, cas1_w2, x2a, 196, 1, 196, (size_t)160*196);
    proj_kernel<128,64><<<dim3(ceil_div(784,32),2), 256>>>(f1, cas1_w1, x1a, 784, 1, 784, (size_t)128*784);
    flash_mma_kernel<64,64><<<dim3(ceil_div(784,64),2), 256, smem64>>>(x1a, x2a, Oa, rma, rsa, 784, 196);
    reduce_mz_kernel<<<2, 256>>>(rma, rsa, MZ, 784);
    combine_kernel<<<dim3(ceil_div(784*64,256),2), 256>>>(Oa, x1a, rma, MZ, 784, 64);

    // ---------------- CSA2: hr=f2 (N1=3136,C=64), lr=X1out (N2=784,C=64), H=64
    proj_kernel<64,64><<<dim3(ceil_div(3136,32),2), 256>>>(f2, cas2_w1, x1b, 3136, 1, 3136, (size_t)64*3136);
    proj_kernel<64,64><<<dim3(ceil_div(784,32),2), 256>>>(Oa, cas2_w2, x2b, 784, 64, 1, (size_t)784*64);
    flash_mma_kernel<64,64><<<dim3(ceil_div(3136,64),2), 256, smem64>>>(x1b, x2b, Ob, rmb, rsb, 3136, 784);
    reduce_mz_kernel<<<2, 256>>>(rmb, rsb, MZ, 3136);
    combine_kernel<<<dim3(ceil_div(3136*64,256),2), 256>>>(Ob, x1b, rmb, MZ, 3136, 64);

    // ---------------- CSA3: hr=f3 (N1=12544,C=32), lr=X2out (N2=3136,C=64), H=32
    proj_kernel<32,32><<<dim3(ceil_div(12544,32),2), 256>>>(f3, cas3_w1, x1c, 12544, 1, 12544, (size_t)32*12544);
    proj_kernel<64,32><<<dim3(ceil_div(3136,32),2), 256>>>(Ob, cas3_w2, x2c, 3136, 64, 1, (size_t)3136*64);
    flash_mma_kernel<32,64><<<dim3(ceil_div(12544,64),2), 256, smem32>>>(x1c, x2c, Oc, rmc, rsc, 12544, 3136);
    reduce_mz_kernel<<<2, 256>>>(rmc, rsc, MZ, 12544);
    combine_kernel<<<dim3(ceil_div(12544*32,256),2), 256>>>(Oc, x1c, rmc, MZ, 12544, 32);

    // ---------------- decoder
    msr_kernel<64,64,32,true><<<dim3(ceil_div(3136,128),2), 128>>>(
        Ob, Oa, m1w1, m1b1, m1w2, m1b2, y1, 56, 28);
    msr_kernel<32,32,16,true><<<dim3(ceil_div(12544,128),2), 128>>>(
        Oc, y1, m2w1, m2b1, m2w2, m2b2, y2, 112, 56);
    msr_kernel<16,16,8,false><<<dim3(ceil_div(50176,128),2), 128>>>(
        nullptr, y2, m3w1, m3b1, m3w2, m3b2, y3, 224, 112);
    msr_kernel<8,2,1,false><<<dim3(ceil_div(200704,128),2), 128>>>(
        nullptr, y3, m4w1, m4b1, m4w2, m4b2, outp, 448, 224);

    (void)in_sizes; (void)n_in; (void)out_size;
}

// round 3
// speedup vs baseline: 2.1321x; 1.3814x over previous
#include <cuda_runtime.h>
#include <cuda_bf16.h>
#include <math.h>
#include <stdint.h>

// ============================================================================
// fp32 scratch
// ============================================================================
static constexpr size_t SZ_X1A = (size_t)2*784*64;
static constexpr size_t SZ_OA  = (size_t)2*784*64;
static constexpr size_t SZ_RMA = (size_t)2*784;
static constexpr size_t SZ_RSA = (size_t)2*784;
static constexpr size_t SZ_X1B = (size_t)2*3136*64;
static constexpr size_t SZ_OB  = (size_t)2*3136*64;
static constexpr size_t SZ_RMB = (size_t)2*3136;
static constexpr size_t SZ_RSB = (size_t)2*3136;
static constexpr size_t SZ_X1C = (size_t)2*12544*32;
static constexpr size_t SZ_OC  = (size_t)2*12544*32;
static constexpr size_t SZ_RMC = (size_t)2*12544;
static constexpr size_t SZ_RSC = (size_t)2*12544;
static constexpr size_t SZ_Y1  = (size_t)2*3136*32;
static constexpr size_t SZ_Y2  = (size_t)2*12544*16;
static constexpr size_t SZ_Y3  = (size_t)2*50176*8;
static constexpr size_t SZ_MZ  = 4;

static constexpr size_t OFF_X1A = 0;
static constexpr size_t OFF_OA  = OFF_X1A + SZ_X1A;
static constexpr size_t OFF_RMA = OFF_OA  + SZ_OA;
static constexpr size_t OFF_RSA = OFF_RMA + SZ_RMA;
static constexpr size_t OFF_X1B = OFF_RSA + SZ_RSA;
static constexpr size_t OFF_OB  = OFF_X1B + SZ_X1B;
static constexpr size_t OFF_RMB = OFF_OB  + SZ_OB;
static constexpr size_t OFF_RSB = OFF_RMB + SZ_RMB;
static constexpr size_t OFF_X1C = OFF_RSB + SZ_RSB;
static constexpr size_t OFF_OC  = OFF_X1C + SZ_X1C;
static constexpr size_t OFF_RMC = OFF_OC  + SZ_OC;
static constexpr size_t OFF_RSC = OFF_RMC + SZ_RMC;
static constexpr size_t OFF_Y1  = OFF_RSC + SZ_RSC;
static constexpr size_t OFF_Y2  = OFF_Y1  + SZ_Y1;
static constexpr size_t OFF_Y3  = OFF_Y2  + SZ_Y2;
static constexpr size_t OFF_MZ  = OFF_Y3  + SZ_Y3;
static constexpr size_t SCRATCH_TOTAL = OFF_MZ + SZ_MZ;
__device__ float g_scratch[SCRATCH_TOTAL];

// ============================================================================
// bf16 scratch (padded row counts; pads written to zero by proj kernels)
// N1p/N2p are multiples of 64.
// ============================================================================
static constexpr size_t BOFF_X1A = 0;                                   // 2*832*64
static constexpr size_t BOFF_X2A = BOFF_X1A + (size_t)2*832*64;         // 2*256*64
static constexpr size_t BOFF_TA  = BOFF_X2A + (size_t)2*256*64;         // 2*64*256
static constexpr size_t BOFF_X1B = BOFF_TA  + (size_t)2*64*256;         // 2*3136*64
static constexpr size_t BOFF_X2B = BOFF_X1B + (size_t)2*3136*64;        // 2*832*64
static constexpr size_t BOFF_TB  = BOFF_X2B + (size_t)2*832*64;         // 2*64*832
static constexpr size_t BOFF_X1C = BOFF_TB  + (size_t)2*64*832;         // 2*12544*32
static constexpr size_t BOFF_X2C = BOFF_X1C + (size_t)2*12544*32;       // 2*3136*32
static constexpr size_t BOFF_TC  = BOFF_X2C + (size_t)2*3136*32;        // 2*32*3136
static constexpr size_t BSCRATCH_TOTAL = BOFF_TC + (size_t)2*32*3136;
__device__ __nv_bfloat16 g_bf[BSCRATCH_TOTAL];

#define MMA_BF16(d, a, b)                                                      \
    asm volatile(                                                              \
        "mma.sync.aligned.m16n8k16.row.col.f32.bf16.bf16.f32 "                 \
        "{%0,%1,%2,%3},{%4,%5,%6,%7},{%8,%9},{%0,%1,%2,%3};"                   \
        : "+f"((d)[0]), "+f"((d)[1]), "+f"((d)[2]), "+f"((d)[3])               \
        : "r"((a)[0]), "r"((a)[1]), "r"((a)[2]), "r"((a)[3]),                  \
          "r"((b)[0]), "r"((b)[1]))

__device__ __forceinline__ void cp16(uint32_t saddr, const void* gptr) {
    asm volatile("cp.async.ca.shared.global [%0], [%1], 16;" :: "r"(saddr), "l"(gptr));
}
__device__ __forceinline__ uint32_t pack_bf2(float lo, float hi) {
    __nv_bfloat162 v = __floats2bfloat162_rn(lo, hi);
    return *reinterpret_cast<uint32_t*>(&v);
}

// ============================================================================
// Projection: out[b,n,h] = sum_c X(b,n,c) * W[c,h].
// X1MODE: writes fp32 out32 [N][H] + bf16 outbf [Np][H] (pad rows zeroed).
// else:   writes bf16 outbf [Np][H] + bf16 transposed outT [H][Np].
// ============================================================================
template<int C, int H, bool X1MODE>
__global__ void __launch_bounds__(256) proj2_kernel(
    const float* __restrict__ X, const float* __restrict__ W,
    float* __restrict__ out32, __nv_bfloat16* __restrict__ outbf,
    __nv_bfloat16* __restrict__ outT,
    int N, int Np, int sn, int sc, size_t bstride)
{
    __shared__ float sw[C*H];
    const int tid = threadIdx.x;
    for (int i = tid; i < C*H; i += 256) sw[i] = W[i];
    __syncthreads();
    const int b = blockIdx.y;
    const int n = blockIdx.x * 32 + (tid & 31);
    const int ty = tid >> 5;
    constexpr int HP = H / 8;
    if (n >= Np) return;

    __nv_bfloat16* obf = outbf + ((size_t)b * Np + n) * H + ty * HP;
    if (n >= N) {
#pragma unroll
        for (int k = 0; k < HP; k++) obf[k] = __float2bfloat16(0.f);
        if (!X1MODE) {
            __nv_bfloat16* ot = outT + (size_t)b * H * Np;
#pragma unroll
            for (int k = 0; k < HP; k++) ot[(size_t)(ty * HP + k) * Np + n] = __float2bfloat16(0.f);
        }
        return;
    }
    const float* xb = X + (size_t)b * bstride;
    float acc[HP];
#pragma unroll
    for (int k = 0; k < HP; k++) acc[k] = 0.f;
    for (int c = 0; c < C; c++) {
        float v = xb[(size_t)n * sn + (size_t)c * sc];
        const float* wr = &sw[c*H + ty*HP];
#pragma unroll
        for (int k = 0; k < HP; k++) acc[k] += v * wr[k];
    }
    if (X1MODE) {
        float* o32 = out32 + ((size_t)b * N + n) * H + ty * HP;
#pragma unroll
        for (int k = 0; k < HP; k++) o32[k] = acc[k];
    }
#pragma unroll
    for (int k = 0; k < HP; k++) obf[k] = __float2bfloat16(acc[k]);
    if (!X1MODE) {
        __nv_bfloat16* ot = outT + (size_t)b * H * Np;
#pragma unroll
        for (int k = 0; k < HP; k++) ot[(size_t)(ty * HP + k) * Np + n] = __float2bfloat16(acc[k]);
    }
}

// ============================================================================
// FA2-style bf16 flash CSA. 128 threads = 4 warps; warp w owns rows
// w*16..w*16+15 and ALL 64 S-columns -> warp-local softmax, P in registers.
// Emits unnormalized O + per-row (max, sum) for global-softmax renorm.
// ============================================================================
template<int H>
__global__ void __launch_bounds__(128) flash_bf16_kernel(
    const __nv_bfloat16* __restrict__ X1bf,   // [b][N1p][H]
    const __nv_bfloat16* __restrict__ X2bf,   // [b][N2p][H]
    const __nv_bfloat16* __restrict__ X2T,    // [b][H][N2p]
    float* __restrict__ Oout, float* __restrict__ rowmax, float* __restrict__ rowsum,
    int N1, int N2, int N1p, int N2p)
{
    constexpr int RB = 64, MB = 64;
    constexpr int PH = H + 8;        // halves
    constexpr int PM = MB + 8;       // 72 halves
    constexpr int KSQ = H / 16;
    constexpr int NTS = MB / 8;      // 8
    constexpr int KSA = MB / 16;     // 4
    constexpr int NTO = H / 8;
    constexpr int CPR = H * 2 / 16;  // 16B chunks per X-row

    extern __shared__ __nv_bfloat16 smh[];
    __nv_bfloat16* sX1 = smh;                    // RB*PH
    __nv_bfloat16* sX2 = sX1 + RB*PH;            // 2 * MB*PH
    __nv_bfloat16* sT  = sX2 + 2*MB*PH;          // 2 * H*PM

    const int b = blockIdx.y;
    const int row0 = blockIdx.x * RB;
    const int tid = threadIdx.x, w = tid >> 5, lane = tid & 31;
    const int g = lane >> 2, t4 = lane & 3;
    const int wrow = w * 16;

    const __nv_bfloat16* x1 = X1bf + (size_t)b * N1p * H;
    const __nv_bfloat16* x2 = X2bf + (size_t)b * N2p * H;
    const __nv_bfloat16* xt = X2T  + (size_t)b * H * N2p;

    // X1 tile -> smem (plain loads; visible after first barrier)
    for (int c = tid; c < RB * CPR; c += 128) {
        int r = c / CPR, k = c % CPR;
        uint4 v = *reinterpret_cast<const uint4*>(x1 + (size_t)(row0 + r) * H + k * 8);
        *reinterpret_cast<uint4*>(sX1 + r * PH + k * 8) = v;
    }

    const int T = (N2 + MB - 1) / MB;

    auto prefetch = [&](int t) {
        int buf = t & 1;
        uint32_t d2 = (uint32_t)__cvta_generic_to_shared(sX2 + buf * MB * PH);
        const __nv_bfloat16* src = x2 + (size_t)t * MB * H;
        for (int c = tid; c < MB * CPR; c += 128) {
            int r = c / CPR, k = c % CPR;
            cp16(d2 + (r * PH + k * 8) * 2, src + (size_t)r * H + k * 8);
        }
        uint32_t dT = (uint32_t)__cvta_generic_to_shared(sT + buf * H * PM);
        for (int c = tid; c < H * 8; c += 128) {
            int r = c / 8, k = c % 8;
            cp16(dT + (r * PM + k * 8) * 2, xt + (size_t)r * N2p + (size_t)t * MB + k * 8);
        }
        asm volatile("cp.async.commit_group;");
    };

    prefetch(0);

    float m0 = -INFINITY, m1 = -INFINITY, s0 = 0.f, s1 = 0.f;
    float o[NTO][4];
#pragma unroll
    for (int nt = 0; nt < NTO; nt++)
#pragma unroll
        for (int k = 0; k < 4; k++) o[nt][k] = 0.f;

    for (int t = 0; t < T; t++) {
        asm volatile("cp.async.wait_group 0;");
        __syncthreads();
        if (t + 1 < T) prefetch(t + 1);
        const __nv_bfloat16* bX2 = sX2 + (t & 1) * MB * PH;
        const __nv_bfloat16* bT  = sT  + (t & 1) * H * PM;

        // ---- S = X1 . X2^T
        float sacc[NTS][4];
#pragma unroll
        for (int nt = 0; nt < NTS; nt++)
#pragma unroll
            for (int k = 0; k < 4; k++) sacc[nt][k] = 0.f;
#pragma unroll
        for (int ks = 0; ks < KSQ; ks++) {
            const int cb = ks * 16 + 2 * t4;
            uint32_t a[4];
            a[0] = *reinterpret_cast<const uint32_t*>(sX1 + (wrow + g) * PH + cb);
            a[1] = *reinterpret_cast<const uint32_t*>(sX1 + (wrow + g + 8) * PH + cb);
            a[2] = *reinterpret_cast<const uint32_t*>(sX1 + (wrow + g) * PH + cb + 8);
            a[3] = *reinterpret_cast<const uint32_t*>(sX1 + (wrow + g + 8) * PH + cb + 8);
#pragma unroll
            for (int nt = 0; nt < NTS; nt++) {
                uint32_t bb[2];
                bb[0] = *reinterpret_cast<const uint32_t*>(bX2 + (nt * 8 + g) * PH + cb);
                bb[1] = *reinterpret_cast<const uint32_t*>(bX2 + (nt * 8 + g) * PH + cb + 8);
                MMA_BF16(sacc[nt], a, bb);
            }
        }

        const int limit = N2 - t * MB;
        const bool full = (limit >= MB);

        // ---- warp-local online softmax (rows g / g+8, shfl over t4 quad)
        float tm0 = -INFINITY, tm1 = -INFINITY;
#pragma unroll
        for (int nt = 0; nt < NTS; nt++) {
            int c0 = nt * 8 + 2 * t4;
            float v0 = (full || c0     < limit) ? sacc[nt][0] : -INFINITY;
            float v1 = (full || c0 + 1 < limit) ? sacc[nt][1] : -INFINITY;
            float v2 = (full || c0     < limit) ? sacc[nt][2] : -INFINITY;
            float v3 = (full || c0 + 1 < limit) ? sacc[nt][3] : -INFINITY;
            tm0 = fmaxf(tm0, fmaxf(v0, v1));
            tm1 = fmaxf(tm1, fmaxf(v2, v3));
        }
        tm0 = fmaxf(tm0, __shfl_xor_sync(0xffffffffu, tm0, 1));
        tm0 = fmaxf(tm0, __shfl_xor_sync(0xffffffffu, tm0, 2));
        tm1 = fmaxf(tm1, __shfl_xor_sync(0xffffffffu, tm1, 1));
        tm1 = fmaxf(tm1, __shfl_xor_sync(0xffffffffu, tm1, 2));
        const float mn0 = fmaxf(m0, tm0), mn1 = fmaxf(m1, tm1);
        const float sc0 = __expf(m0 - mn0), sc1 = __expf(m1 - mn1);
        m0 = mn0; m1 = mn1;

        float ps0 = 0.f, ps1 = 0.f;
        uint32_t pA[KSA][4];
#pragma unroll
        for (int nt = 0; nt < NTS; nt++) {
            int c0 = nt * 8 + 2 * t4;
            float p0 = (full || c0     < limit) ? __expf(sacc[nt][0] - mn0) : 0.f;
            float p1 = (full || c0 + 1 < limit) ? __expf(sacc[nt][1] - mn0) : 0.f;
            float p2 = (full || c0     < limit) ? __expf(sacc[nt][2] - mn1) : 0.f;
            float p3 = (full || c0 + 1 < limit) ? __expf(sacc[nt][3] - mn1) : 0.f;
            ps0 += p0 + p1; ps1 += p2 + p3;
            pA[nt >> 1][(nt & 1) * 2 + 0] = pack_bf2(p0, p1);
            pA[nt >> 1][(nt & 1) * 2 + 1] = pack_bf2(p2, p3);
        }
        ps0 += __shfl_xor_sync(0xffffffffu, ps0, 1);
        ps0 += __shfl_xor_sync(0xffffffffu, ps0, 2);
        ps1 += __shfl_xor_sync(0xffffffffu, ps1, 1);
        ps1 += __shfl_xor_sync(0xffffffffu, ps1, 2);
        s0 = s0 * sc0 + ps0;
        s1 = s1 * sc1 + ps1;

#pragma unroll
        for (int nt = 0; nt < NTO; nt++) {
            o[nt][0] *= sc0; o[nt][1] *= sc0;
            o[nt][2] *= sc1; o[nt][3] *= sc1;
        }
        // ---- O += P . X2
#pragma unroll
        for (int ks = 0; ks < KSA; ks++) {
#pragma unroll
            for (int nt = 0; nt < NTO; nt++) {
                const int rb2 = (nt * 8 + g) * PM + ks * 16 + 2 * t4;
                uint32_t bb[2];
                bb[0] = *reinterpret_cast<const uint32_t*>(bT + rb2);
                bb[1] = *reinterpret_cast<const uint32_t*>(bT + rb2 + 8);
                MMA_BF16(o[nt], pA[ks], bb);
            }
        }
    }

    // ---- store unnormalized O + stats
    {
        int gr0 = row0 + wrow + g;
        if (gr0 < N1) {
            float* dst = Oout + ((size_t)b * N1 + gr0) * H;
#pragma unroll
            for (int nt = 0; nt < NTO; nt++)
                *reinterpret_cast<float2*>(dst + nt * 8 + 2 * t4) = make_float2(o[nt][0], o[nt][1]);
        }
        int gr1 = gr0 + 8;
        if (gr1 < N1) {
            float* dst = Oout + ((size_t)b * N1 + gr1) * H;
#pragma unroll
            for (int nt = 0; nt < NTO; nt++)
                *reinterpret_cast<float2*>(dst + nt * 8 + 2 * t4) = make_float2(o[nt][2], o[nt][3]);
        }
        if (t4 == 0) {
            if (gr0 < N1) { rowmax[(size_t)b * N1 + gr0] = m0; rowsum[(size_t)b * N1 + gr0] = s0; }
            if (gr1 < N1) { rowmax[(size_t)b * N1 + gr1] = m1; rowsum[(size_t)b * N1 + gr1] = s1; }
        }
    }
}

// ============================================================================
// Global softmax stats
// ============================================================================
__global__ void __launch_bounds__(1024) reduce_mz_kernel(
    const float* __restrict__ rm, const float* __restrict__ rs,
    float* __restrict__ MZ, int N1)
{
    __shared__ float red[1024];
    const int b = blockIdx.x, tid = threadIdx.x;
    const float* rmb = rm + (size_t)b * N1;
    const float* rsb = rs + (size_t)b * N1;
    float mx = -INFINITY;
    for (int i = tid; i < N1; i += 1024) mx = fmaxf(mx, rmb[i]);
    red[tid] = mx; __syncthreads();
    for (int s = 512; s > 0; s >>= 1) {
        if (tid < s) red[tid] = fmaxf(red[tid], red[tid + s]);
        __syncthreads();
    }
    const float M = red[0];
    __syncthreads();
    float z = 0.f;
    for (int i = tid; i < N1; i += 1024) z += rsb[i] * __expf(rmb[i] - M);
    red[tid] = z; __syncthreads();
    for (int s = 512; s > 0; s >>= 1) {
        if (tid < s) red[tid] += red[tid + s];
        __syncthreads();
    }
    if (tid == 0) { MZ[b * 2] = M; MZ[b * 2 + 1] = red[0]; }
}

__global__ void __launch_bounds__(256) combine_kernel(
    float* __restrict__ O, const float* __restrict__ x1,
    const float* __restrict__ rm, const float* __restrict__ MZ,
    int N1, int H)
{
    const int b = blockIdx.y;
    const float M = MZ[b * 2];
    const float invZ = 1.f / MZ[b * 2 + 1];
    const size_t total = (size_t)N1 * H;
    const size_t idx = (size_t)blockIdx.x * 256 + threadIdx.x;
    if (idx >= total) return;
    const int n = (int)(idx / H);
    const float f = __expf(rm[(size_t)b * N1 + n] - M) * invZ;
    const size_t g = (size_t)b * total + idx;
    O[g] = O[g] * f + x1[g];
}

// ============================================================================
// MSR
// ============================================================================
template<int CIN, int CHID, int COUT, bool HASBASE>
__global__ void msr_kernel(
    const float* __restrict__ base, const float* __restrict__ prev,
    const float* __restrict__ w1, const float* __restrict__ b1,
    const float* __restrict__ w2, const float* __restrict__ b2,
    float* __restrict__ out, int Hout, int Hin)
{
    __shared__ float sw1[CIN * CHID];
    __shared__ float sw2[CHID * COUT];
    __shared__ float sb1[CHID];
    __shared__ float sb2[COUT];
    const int tid = threadIdx.x;
    for (int i = tid; i < CIN * CHID; i += 128) sw1[i] = w1[i];
    for (int i = tid; i < CHID * COUT; i += 128) sw2[i] = w2[i];
    if (tid < CHID) sb1[tid] = b1[tid];
    if (tid < COUT) sb2[tid] = b2[tid];
    __syncthreads();

    const int b = blockIdx.y;
    const int N = Hout * Hout;
    const int n = blockIdx.x * 128 + tid;
    if (n >= N) return;
    const int oy = n / Hout, ox = n % Hout;

    int y0 = (oy - 1) >> 1; int y1v = y0 + 1;
    const float wy1 = (oy & 1) ? 0.25f : 0.75f; const float wy0 = 1.f - wy1;
    y0 = max(y0, 0); y1v = min(y1v, Hin - 1);
    int x0 = (ox - 1) >> 1; int x1v = x0 + 1;
    const float wx1 = (ox & 1) ? 0.25f : 0.75f; const float wx0 = 1.f - wx1;
    x0 = max(x0, 0); x1v = min(x1v, Hin - 1);

    const size_t pb = (size_t)b * Hin * Hin;
    const float* p00 = prev + (pb + (size_t)y0  * Hin + x0 ) * CIN;
    const float* p01 = prev + (pb + (size_t)y0  * Hin + x1v) * CIN;
    const float* p10 = prev + (pb + (size_t)y1v * Hin + x0 ) * CIN;
    const float* p11 = prev + (pb + (size_t)y1v * Hin + x1v) * CIN;
    const float w00 = wy0 * wx0, w01 = wy0 * wx1, w10 = wy1 * wx0, w11 = wy1 * wx1;
    const float* bp = HASBASE ? (base + ((size_t)b * N + n) * CIN) : nullptr;

    float hid[CHID];
#pragma unroll
    for (int j = 0; j < CHID; j++) hid[j] = sb1[j];
    for (int c = 0; c < CIN; c++) {
        float v = w00 * p00[c] + w01 * p01[c] + w10 * p10[c] + w11 * p11[c];
        if (HASBASE) v += bp[c];
        const float* wr = &sw1[c * CHID];
#pragma unroll
        for (int j = 0; j < CHID; j++) hid[j] += v * wr[j];
    }
#pragma unroll
    for (int j = 0; j < CHID; j++) hid[j] = fminf(fmaxf(hid[j], 0.f), 6.f);

    float accv[COUT];
#pragma unroll
    for (int k = 0; k < COUT; k++) accv[k] = sb2[k];
#pragma unroll
    for (int j = 0; j < CHID; j++) {
        const float hv = hid[j];
        const float* wr = &sw2[j * COUT];
#pragma unroll
        for (int k = 0; k < COUT; k++) accv[k] += hv * wr[k];
    }
    float* ob = out + ((size_t)b * N + n) * COUT;
#pragma unroll
    for (int k = 0; k < COUT; k++) ob[k] = accv[k];
}

// ============================================================================
// Launch
// ============================================================================
static inline int ceil_div(int a, int b) { return (a + b - 1) / b; }

template<int H>
static inline int flash_smem_bytes() {
    constexpr int RB = 64, MB = 64, PH = H + 8, PM = MB + 8;
    return (RB*PH + 2*MB*PH + 2*H*PM) * 2;
}

extern "C" void kernel_launch(void* const* d_in, const int* in_sizes, int n_in,
                              void* d_out, int out_size)
{
    const float* f0 = (const float*)d_in[0];   // [2,160,14,14]
    const float* f1 = (const float*)d_in[1];   // [2,128,28,28]
    const float* f2 = (const float*)d_in[2];   // [2,64,56,56]
    const float* f3 = (const float*)d_in[3];   // [2,32,112,112]
    const float* cas1_w1 = (const float*)d_in[4];
    const float* cas1_w2 = (const float*)d_in[5];
    const float* cas2_w1 = (const float*)d_in[6];
    const float* cas2_w2 = (const float*)d_in[7];
    const float* cas3_w1 = (const float*)d_in[8];
    const float* cas3_w2 = (const float*)d_in[9];
    const float* m1w1 = (const float*)d_in[10]; const float* m1b1 = (const float*)d_in[11];
    const float* m1w2 = (const float*)d_in[12]; const float* m1b2 = (const float*)d_in[13];
    const float* m2w1 = (const float*)d_in[14]; const float* m2b1 = (const float*)d_in[15];
    const float* m2w2 = (const float*)d_in[16]; const float* m2b2 = (const float*)d_in[17];
    const float* m3w1 = (const float*)d_in[18]; const float* m3b1 = (const float*)d_in[19];
    const float* m3w2 = (const float*)d_in[20]; const float* m3b2 = (const float*)d_in[21];
    const float* m4w1 = (const float*)d_in[22]; const float* m4b1 = (const float*)d_in[23];
    const float* m4w2 = (const float*)d_in[24]; const float* m4b2 = (const float*)d_in[25];
    float* outp = (float*)d_out;

    float* S = nullptr;
    cudaGetSymbolAddress((void**)&S, g_scratch);
    __nv_bfloat16* B = nullptr;
    cudaGetSymbolAddress((void**)&B, g_bf);

    float* x1a = S + OFF_X1A; float* Oa = S + OFF_OA;
    float* rma = S + OFF_RMA; float* rsa = S + OFF_RSA;
    float* x1b = S + OFF_X1B; float* Ob = S + OFF_OB;
    float* rmb = S + OFF_RMB; float* rsb = S + OFF_RSB;
    float* x1c = S + OFF_X1C; float* Oc = S + OFF_OC;
    float* rmc = S + OFF_RMC; float* rsc = S + OFF_RSC;
    float* y1 = S + OFF_Y1; float* y2 = S + OFF_Y2; float* y3 = S + OFF_Y3;
    float* MZ = S + OFF_MZ;

    __nv_bfloat16* x1abf = B + BOFF_X1A; __nv_bfloat16* x2abf = B + BOFF_X2A; __nv_bfloat16* x2aT = B + BOFF_TA;
    __nv_bfloat16* x1bbf = B + BOFF_X1B; __nv_bfloat16* x2bbf = B + BOFF_X2B; __nv_bfloat16* x2bT = B + BOFF_TB;
    __nv_bfloat16* x1cbf = B + BOFF_X1C; __nv_bfloat16* x2cbf = B + BOFF_X2C; __nv_bfloat16* x2cT = B + BOFF_TC;

    const int smem64 = flash_smem_bytes<64>();   // 46080
    const int smem32 = flash_smem_bytes<32>();   // 24576
    cudaFuncSetAttribute((const void*)flash_bf16_kernel<64>,
                         cudaFuncAttributeMaxDynamicSharedMemorySize, smem64);
    cudaFuncSetAttribute((const void*)flash_bf16_kernel<32>,
                         cudaFuncAttributeMaxDynamicSharedMemorySize, smem32);

    // ---------------- CSA1: N1=784 (p832), N2=196 (p256), H=64
    proj2_kernel<160,64,false><<<dim3(ceil_div(256,32),2), 256>>>(
        f0, cas1_w2, nullptr, x2abf, x2aT, 196, 256, 1, 196, (size_t)160*196);
    proj2_kernel<128,64,true><<<dim3(ceil_div(832,32),2), 256>>>(
        f1, cas1_w1, x1a, x1abf, nullptr, 784, 832, 1, 784, (size_t)128*784);
    flash_bf16_kernel<64><<<dim3(832/64,2), 128, smem64>>>(
        x1abf, x2abf, x2aT, Oa, rma, rsa, 784, 196, 832, 256);
    reduce_mz_kernel<<<2, 1024>>>(rma, rsa, MZ, 784);
    combine_kernel<<<dim3(ceil_div(784*64,256),2), 256>>>(Oa, x1a, rma, MZ, 784, 64);

    // ---------------- CSA2: N1=3136, N2=784 (p832), H=64
    proj2_kernel<64,64,true><<<dim3(ceil_div(3136,32),2), 256>>>(
        f2, cas2_w1, x1b, x1bbf, nullptr, 3136, 3136, 1, 3136, (size_t)64*3136);
    proj2_kernel<64,64,false><<<dim3(ceil_div(832,32),2), 256>>>(
        Oa, cas2_w2, nullptr, x2bbf, x2bT, 784, 832, 64, 1, (size_t)784*64);
    flash_bf16_kernel<64><<<dim3(3136/64,2), 128, smem64>>>(
        x1bbf, x2bbf, x2bT, Ob, rmb, rsb, 3136, 784, 3136, 832);
    reduce_mz_kernel<<<2, 1024>>>(rmb, rsb, MZ, 3136);
    combine_kernel<<<dim3(ceil_div(3136*64,256),2), 256>>>(Ob, x1b, rmb, MZ, 3136, 64);

    // ---------------- CSA3: N1=12544, N2=3136, H=32
    proj2_kernel<32,32,true><<<dim3(ceil_div(12544,32),2), 256>>>(
        f3, cas3_w1, x1c, x1cbf, nullptr, 12544, 12544, 1, 12544, (size_t)32*12544);
    proj2_kernel<64,32,false><<<dim3(ceil_div(3136,32),2), 256>>>(
        Ob, cas3_w2, nullptr, x2cbf, x2cT, 3136, 3136, 64, 1, (size_t)3136*64);
    flash_bf16_kernel<32><<<dim3(12544/64,2), 128, smem32>>>(
        x1cbf, x2cbf, x2cT, Oc, rmc, rsc, 12544, 3136, 12544, 3136);
    reduce_mz_kernel<<<2, 1024>>>(rmc, rsc, MZ, 12544);
    combine_kernel<<<dim3(ceil_div(12544*32,256),2), 256>>>(Oc, x1c, rmc, MZ, 12544, 32);

    // ---------------- decoder
    msr_kernel<64,64,32,true><<<dim3(ceil_div(3136,128),2), 128>>>(
        Ob, Oa, m1w1, m1b1, m1w2, m1b2, y1, 56, 28);
    msr_kernel<32,32,16,true><<<dim3(ceil_div(12544,128),2), 128>>>(
        Oc, y1, m2w1, m2b1, m2w2, m2b2, y2, 112, 56);
    msr_kernel<16,16,8,false><<<dim3(ceil_div(50176,128),2), 128>>>(
        nullptr, y2, m3w1, m3b1, m3w2, m3b2, y3, 224, 112);
    msr_kernel<8,2,1,false><<<dim3(ceil_div(200704,128),2), 128>>>(
        nullptr, y3, m4w1, m4b1, m4w2, m4b2, outp, 448, 224);

    (void)in_sizes; (void)n_in; (void)out_size;
}